// round 1
// baseline (speedup 1.0000x reference)
#include <cuda_runtime.h>

#define LOG2E 1.4426950408889634f
#define EPS   1e-8f

// Per-row partial results (per_query values). B=2048 in this problem; headroom to 8192.
__device__ float g_partials[8192];

__global__ void __launch_bounds__(128) ndcg_row_kernel(
    const float* __restrict__ scores,
    const int*   __restrict__ relev,
    const int*   __restrict__ qlen,
    int D)
{
    const int b = blockIdx.x;
    const int i = threadIdx.x;   // 0..127, D <= 128

    __shared__ float s_s[128];
    __shared__ float s_g[128];
    __shared__ int   s_cnt[8];
    __shared__ float s_rnum[4];
    __shared__ float s_ridl[4];

    const int L = qlen[b];
    const bool in_row = (i < D);
    const bool valid  = (i < L);   // L <= D guaranteed by problem

    float si = 0.0f;
    int   ri = 0;
    if (in_row) {
        si = scores[b * D + i];
        ri = relev[b * D + i];
    }
    // gains = 2^rel - 1, zeroed outside valid prefix (matches reference)
    const float gi = valid ? (float)((1 << ri) - 1) : 0.0f;

    if (in_row) { s_s[i] = si; s_g[i] = gi; }
    if (i < 8) s_cnt[i] = 0;
    __syncthreads();

    if (valid) atomicAdd(&s_cnt[ri], 1);
    __syncthreads();

    // ---- pairwise sum over unordered valid pairs, cyclic-distance enumeration ----
    // For thread i < L: iterate k = 1..floor(L/2), partner j = (i+k) mod L.
    // Each unordered pair {p,q} at cyclic distance d is visited exactly once
    // (smaller of d, L-d), except d == L/2 (L even) which is visited by both
    // endpoints -> guard i < k there.
    // Contribution per unordered pair (both orders folded):
    //   delta * (L2(d) + L2(-d)) = -delta * (|d|*log2e + 2*log2(1 + e^{-|d|}))
    float num = 0.0f;
    if (valid && L > 1) {
        const int half = L >> 1;
        #pragma unroll 4
        for (int k = 1; k <= half; ++k) {
            if ((k + k == L) && (i >= k)) break;   // tie distance, count once
            int j = i + k; if (j >= L) j -= L;
            const float sj = s_s[j];
            const float gj = s_g[j];
            const float a     = fabsf(si - sj);
            const float delta = fabsf(gi - gj);
            const float u = __expf(-a);                       // e^{-|d|}  (MUFU ex2)
            const float t = fmaf(a, LOG2E, 2.0f * __log2f(1.0f + u)); // MUFU lg2
            num = fmaf(-delta, t, num);
        }
    }

    // ---- ideal DCG via counting sort (gains in {0,1,3,7,15}) ----
    // rank i gets gain determined by descending-count brackets
    float idl = 0.0f;
    if (valid) {
        const int c4 = s_cnt[4];
        const int c3 = c4 + s_cnt[3];
        const int c2 = c3 + s_cnt[2];
        const int c1 = c2 + s_cnt[1];
        float gr;
        if      (i < c4) gr = 15.0f;
        else if (i < c3) gr = 7.0f;
        else if (i < c2) gr = 3.0f;
        else if (i < c1) gr = 1.0f;
        else             gr = 0.0f;
        idl = gr / __log2f((float)(i + 2));
    }

    // ---- block reduction of (num, idl) ----
    #pragma unroll
    for (int off = 16; off > 0; off >>= 1) {
        num += __shfl_down_sync(0xFFFFFFFFu, num, off);
        idl += __shfl_down_sync(0xFFFFFFFFu, idl, off);
    }
    const int wid  = i >> 5;
    const int lane = i & 31;
    if (lane == 0) { s_rnum[wid] = num; s_ridl[wid] = idl; }
    __syncthreads();
    if (i == 0) {
        const float n  = s_rnum[0] + s_rnum[1] + s_rnum[2] + s_rnum[3];
        const float id = s_ridl[0] + s_ridl[1] + s_ridl[2] + s_ridl[3];
        g_partials[b] = -n / (id + EPS);
    }
}

__global__ void __launch_bounds__(256) ndcg_reduce_kernel(float* __restrict__ out, int B)
{
    __shared__ float s_red[8];
    float s = 0.0f;
    for (int i = threadIdx.x; i < B; i += 256) s += g_partials[i];
    #pragma unroll
    for (int off = 16; off > 0; off >>= 1)
        s += __shfl_down_sync(0xFFFFFFFFu, s, off);
    const int wid  = threadIdx.x >> 5;
    const int lane = threadIdx.x & 31;
    if (lane == 0) s_red[wid] = s;
    __syncthreads();
    if (threadIdx.x == 0) {
        float t = 0.0f;
        #pragma unroll
        for (int w = 0; w < 8; ++w) t += s_red[w];
        out[0] = t / (float)B;
    }
}

extern "C" void kernel_launch(void* const* d_in, const int* in_sizes, int n_in,
                              void* d_out, int out_size)
{
    const float* scores = (const float*)d_in[0];
    const int*   relev  = (const int*)  d_in[1];
    const int*   qlen   = (const int*)  d_in[2];
    float*       out    = (float*)      d_out;

    const int B = in_sizes[2];
    const int D = in_sizes[0] / B;   // 128

    ndcg_row_kernel<<<B, 128>>>(scores, relev, qlen, D);
    ndcg_reduce_kernel<<<1, 256>>>(out, B);
}

// round 3
// speedup vs baseline: 1.2931x; 1.2931x over previous
#include <cuda_runtime.h>

#define LOG2E 1.4426950408889634f
#define EPS   1e-8f

// Per-row partial results. B=2048 here; headroom to 8192.
__device__ float        g_partials[8192];
__device__ unsigned int g_done;   // zero-initialized; last block resets -> graph-replay safe

__global__ void __launch_bounds__(128) ndcg_fused_kernel(
    const float* __restrict__ scores,
    const int*   __restrict__ relev,
    const int*   __restrict__ qlen,
    float*       __restrict__ out,
    int D, int B)
{
    const int b = blockIdx.x;
    const int i = threadIdx.x;   // 0..127, D <= 128

    __shared__ float2 s_sg[128];          // (score, gain) packed -> one LDS.64 per partner
    __shared__ int    s_cnt[8];
    __shared__ float  s_rnum[4];
    __shared__ float  s_ridl[4];
    __shared__ int    s_last;

    const int  L      = qlen[b];
    const bool in_row = (i < D);
    const bool valid  = (i < L);

    float si = 0.0f;
    int   ri = 0;
    if (in_row) {
        si = scores[b * D + i];
        ri = relev[b * D + i];
    }
    const float gi = valid ? (float)((1 << ri) - 1) : 0.0f;   // 2^rel - 1 on valid prefix

    if (in_row) s_sg[i] = make_float2(si, gi);
    if (i < 8) s_cnt[i] = 0;
    __syncthreads();

    if (valid) atomicAdd(&s_cnt[ri], 1);
    __syncthreads();

    // ---- pairwise sum over unordered valid pairs, cyclic-distance enumeration ----
    // Thread i (< L) handles partners j=(i+k)%L for k=1..floor((L-1)/2); the tie
    // distance k=L/2 (L even) is handled once, by threads i < L/2, after the loop.
    // Folded both-orders contribution of pair {i,j} with a=|si-sj|:
    //   delta * (log2s(d) + log2s(-d)) = -delta * (a*log2e + 2*log2(1 + 2^{-a*log2e}))
    float num = 0.0f;
    if (valid && L > 1) {
        const int halfm = (L - 1) >> 1;
        #pragma unroll 4
        for (int k = 1; k <= halfm; ++k) {
            int j = i + k; if (j >= L) j -= L;
            const float2 p  = s_sg[j];
            const float a     = fabsf(si - p.x);
            const float delta = fabsf(gi - p.y);
            const float nm = a * (-LOG2E);            // -a*log2e
            const float u  = exp2f(nm);               // MUFU EX2
            const float l  = __log2f(1.0f + u);       // MUFU LG2
            num = fmaf(-delta, fmaf(2.0f, l, -nm), num);
        }
        // tie distance (L even): pair (i, i+L/2), counted once
        if (((L & 1) == 0) && (i < (L >> 1))) {
            const float2 p  = s_sg[i + (L >> 1)];
            const float a     = fabsf(si - p.x);
            const float delta = fabsf(gi - p.y);
            const float nm = a * (-LOG2E);
            const float u  = exp2f(nm);
            const float l  = __log2f(1.0f + u);
            num = fmaf(-delta, fmaf(2.0f, l, -nm), num);
        }
    }

    // ---- ideal DCG via counting sort (gains in {0,1,3,7,15}) ----
    float idl = 0.0f;
    if (valid) {
        const int c4 = s_cnt[4];
        const int c3 = c4 + s_cnt[3];
        const int c2 = c3 + s_cnt[2];
        const int c1 = c2 + s_cnt[1];
        float gr;
        if      (i < c4) gr = 15.0f;
        else if (i < c3) gr = 7.0f;
        else if (i < c2) gr = 3.0f;
        else if (i < c1) gr = 1.0f;
        else             gr = 0.0f;
        idl = gr / __log2f((float)(i + 2));
    }

    // ---- block reduction of (num, idl) ----
    #pragma unroll
    for (int off = 16; off > 0; off >>= 1) {
        num += __shfl_down_sync(0xFFFFFFFFu, num, off);
        idl += __shfl_down_sync(0xFFFFFFFFu, idl, off);
    }
    const int wid  = i >> 5;
    const int lane = i & 31;
    if (lane == 0) { s_rnum[wid] = num; s_ridl[wid] = idl; }
    __syncthreads();
    if (i == 0) {
        const float n  = s_rnum[0] + s_rnum[1] + s_rnum[2] + s_rnum[3];
        const float id = s_ridl[0] + s_ridl[1] + s_ridl[2] + s_ridl[3];
        g_partials[b] = -n / (id + EPS);
        // signal completion; detect last block
        __threadfence();
        unsigned int t = atomicAdd(&g_done, 1u);
        s_last = (t == (unsigned int)(gridDim.x - 1));
    }
    __syncthreads();

    // ---- last block: deterministic final reduction over all B partials ----
    if (s_last) {
        __threadfence();   // acquire partials written by other blocks
        float s = 0.0f;
        for (int r = i; r < B; r += 128) s = s + g_partials[r];  // fixed per-thread order
        #pragma unroll
        for (int off = 16; off > 0; off >>= 1)
            s += __shfl_down_sync(0xFFFFFFFFu, s, off);
        if (lane == 0) s_rnum[wid] = s;
        __syncthreads();
        if (i == 0) {
            float t = s_rnum[0] + s_rnum[1] + s_rnum[2] + s_rnum[3];
            out[0] = t / (float)B;
            g_done = 0;    // reset for next graph replay
        }
    }
}

extern "C" void kernel_launch(void* const* d_in, const int* in_sizes, int n_in,
                              void* d_out, int out_size)
{
    const float* scores = (const float*)d_in[0];
    const int*   relev  = (const int*)  d_in[1];
    const int*   qlen   = (const int*)  d_in[2];
    float*       out    = (float*)      d_out;

    const int B = in_sizes[2];
    const int D = in_sizes[0] / B;   // 128

    ndcg_fused_kernel<<<B, 128>>>(scores, relev, qlen, out, D, B);
}